// round 2
// baseline (speedup 1.0000x reference)
#include <cuda_runtime.h>

// Problem constants
#define BB 8
#define TT 256
#define UU 128
#define HH 512
#define II 640
#define VV 1024

// Scratch for the two small projections (no cudaMalloc allowed)
__device__ float g_enc_proj[BB * TT * II];   // (2048, 640)  5.2 MB
__device__ float g_dec_proj[BB * UU * II];   // (1024, 640)  2.6 MB

// Fast, accurate tanh: tanh(x) = 1 - 2/(exp(2x)+1).
// __expf -> MUFU ex2 (rel err ~1e-7), __fdividef -> MUFU rcp. Saturates
// correctly at +/-1 for large |x| (exp -> inf or 0).
__device__ __forceinline__ float tanh_fast(float x) {
    float e = __expf(2.0f * x);
    return 1.0f - __fdividef(2.0f, e + 1.0f);
}

// ---------------------------------------------------------------------------
// Kernel 1: enc_proj = enc_h @ enc_w + enc_b ; dec_proj = dec_h @ dec_w + dec_b
// Rows 0..2047 = encoder, rows 2048..3071 = decoder. 64x64x16 tile, 256 thr,
// 4x4 microtile. Tiny (2 GFLOP).
// ---------------------------------------------------------------------------
__global__ __launch_bounds__(256) void proj_kernel(
    const float* __restrict__ enc_h, const float* __restrict__ dec_h,
    const float* __restrict__ enc_w, const float* __restrict__ enc_b,
    const float* __restrict__ dec_w, const float* __restrict__ dec_b)
{
    __shared__ float As[16][68];   // [k][row], padded
    __shared__ float Bs[16][64];   // [k][col]

    const int r0 = blockIdx.y * 64;
    const int n0 = blockIdx.x * 64;

    const float* in; const float* w; const float* bias; float* outp;
    if (r0 < BB * TT) {
        in = enc_h + (size_t)r0 * HH; w = enc_w; bias = enc_b;
        outp = g_enc_proj + (size_t)r0 * II;
    } else {
        const int r = r0 - BB * TT;
        in = dec_h + (size_t)r * HH; w = dec_w; bias = dec_b;
        outp = g_dec_proj + (size_t)r * II;
    }

    const int t  = threadIdx.x;
    const int tx = t & 15, ty = t >> 4;

    const int a_row = t >> 2;          // 0..63
    const int a_k4  = (t & 3) * 4;     // 0,4,8,12
    const int b_kk  = t >> 4;          // 0..15
    const int b_j4  = (t & 15) * 4;    // 0..60

    float acc[4][4] = {};

    for (int k0 = 0; k0 < HH; k0 += 16) {
        float4 av = *(const float4*)(in + (size_t)a_row * HH + k0 + a_k4);
        As[a_k4 + 0][a_row] = av.x;
        As[a_k4 + 1][a_row] = av.y;
        As[a_k4 + 2][a_row] = av.z;
        As[a_k4 + 3][a_row] = av.w;
        *(float4*)&Bs[b_kk][b_j4] =
            *(const float4*)(w + (size_t)(k0 + b_kk) * II + n0 + b_j4);
        __syncthreads();
        #pragma unroll
        for (int kk = 0; kk < 16; kk++) {
            float4 a4 = *(const float4*)&As[kk][ty * 4];
            float4 b4 = *(const float4*)&Bs[kk][tx * 4];
            float a[4] = {a4.x, a4.y, a4.z, a4.w};
            float bw[4] = {b4.x, b4.y, b4.z, b4.w};
            #pragma unroll
            for (int i = 0; i < 4; i++)
                #pragma unroll
                for (int j = 0; j < 4; j++)
                    acc[i][j] = fmaf(a[i], bw[j], acc[i][j]);
        }
        __syncthreads();
    }

    float4 bv = *(const float4*)(bias + n0 + tx * 4);
    float bb[4] = {bv.x, bv.y, bv.z, bv.w};
    #pragma unroll
    for (int i = 0; i < 4; i++) {
        float4 o;
        o.x = acc[i][0] + bb[0];
        o.y = acc[i][1] + bb[1];
        o.z = acc[i][2] + bb[2];
        o.w = acc[i][3] + bb[3];
        *(float4*)(outp + (size_t)(ty * 4 + i) * II + n0 + tx * 4) = o;
    }
}

// ---------------------------------------------------------------------------
// Kernel 2: fused joint GEMM.
//   out[bt*U + u, n] = sum_k tanh(enc_proj[bt,k] + dec_proj[b*U+u,k]) * W[k,n] + b[n]
// BM=128 (=U, so one block row-tile = one (b,t); enc row is a broadcast),
// BN=128, BK=16, 256 threads, 8x8 microtile. Joint tensor never hits GMEM.
// ---------------------------------------------------------------------------
__global__ __launch_bounds__(256) void joint_kernel(
    const float* __restrict__ dense_w, const float* __restrict__ dense_b,
    float* __restrict__ out)
{
    __shared__ float As[16][132];   // [k][u], padded (132*4B rows, 16B-aligned)
    __shared__ float Bs[16][128];   // [k][n]

    const int bt = blockIdx.y;            // 0..2047
    const int b  = bt >> 8;               // bt / T
    const int n0 = blockIdx.x * 128;

    const float* __restrict__ encp = g_enc_proj + (size_t)bt * II;
    const float* __restrict__ decp = g_dec_proj + (size_t)(b * UU) * II;

    const int t  = threadIdx.x;
    const int tx = t & 15, ty = t >> 4;

    const int a_row0 = t >> 2;            // 0..63 (+64 on second pass)
    const int a_k4   = (t & 3) * 4;       // 0,4,8,12
    const int b_kk0  = t >> 5;            // 0..7 (+8 on second pass)
    const int b_j4   = (t & 31) * 4;      // 0..124

    float acc[8][8] = {};

    for (int k0 = 0; k0 < II; k0 += 16) {
        // A tile: tanh(dec row + broadcast enc row). enc float4 hits L1 broadcast.
        float4 e = *(const float4*)(encp + k0 + a_k4);
        #pragma unroll
        for (int l = 0; l < 2; l++) {
            const int row = a_row0 + l * 64;
            float4 d = *(const float4*)(decp + (size_t)row * II + k0 + a_k4);
            As[a_k4 + 0][row] = tanh_fast(d.x + e.x);
            As[a_k4 + 1][row] = tanh_fast(d.y + e.y);
            As[a_k4 + 2][row] = tanh_fast(d.z + e.z);
            As[a_k4 + 3][row] = tanh_fast(d.w + e.w);
        }
        // B tile: dense_w rows are contiguous in n -> coalesced float4.
        #pragma unroll
        for (int l = 0; l < 2; l++) {
            const int kk = b_kk0 + l * 8;
            *(float4*)&Bs[kk][b_j4] =
                *(const float4*)(dense_w + (size_t)(k0 + kk) * VV + n0 + b_j4);
        }
        __syncthreads();

        #pragma unroll
        for (int kk = 0; kk < 16; kk++) {
            float a[8], w8[8];
            *(float4*)&a[0]  = *(const float4*)&As[kk][ty * 8];
            *(float4*)&a[4]  = *(const float4*)&As[kk][ty * 8 + 4];
            *(float4*)&w8[0] = *(const float4*)&Bs[kk][tx * 8];
            *(float4*)&w8[4] = *(const float4*)&Bs[kk][tx * 8 + 4];
            #pragma unroll
            for (int i = 0; i < 8; i++)
                #pragma unroll
                for (int j = 0; j < 8; j++)
                    acc[i][j] = fmaf(a[i], w8[j], acc[i][j]);
        }
        __syncthreads();
    }

    // Epilogue: +bias, vectorized stores. m = bt*128 + u, out row stride = V.
    float bb[8];
    *(float4*)&bb[0] = *(const float4*)(dense_b + n0 + tx * 8);
    *(float4*)&bb[4] = *(const float4*)(dense_b + n0 + tx * 8 + 4);

    float* outp = out + (size_t)bt * 128 * VV + n0 + tx * 8;
    #pragma unroll
    for (int i = 0; i < 8; i++) {
        const size_t row = (size_t)(ty * 8 + i);
        float4 o0, o1;
        o0.x = acc[i][0] + bb[0]; o0.y = acc[i][1] + bb[1];
        o0.z = acc[i][2] + bb[2]; o0.w = acc[i][3] + bb[3];
        o1.x = acc[i][4] + bb[4]; o1.y = acc[i][5] + bb[5];
        o1.z = acc[i][6] + bb[6]; o1.w = acc[i][7] + bb[7];
        *(float4*)(outp + row * VV)     = o0;
        *(float4*)(outp + row * VV + 4) = o1;
    }
}

extern "C" void kernel_launch(void* const* d_in, const int* in_sizes, int n_in,
                              void* d_out, int out_size) {
    const float* enc_h   = (const float*)d_in[0];  // (B,T,H)
    const float* dec_h   = (const float*)d_in[1];  // (B,U,H)
    const float* enc_w   = (const float*)d_in[2];  // (H,I)
    const float* enc_b   = (const float*)d_in[3];  // (I,)
    const float* dec_w   = (const float*)d_in[4];  // (H,I)
    const float* dec_b   = (const float*)d_in[5];  // (I,)
    const float* dense_w = (const float*)d_in[6];  // (I,V)
    const float* dense_b = (const float*)d_in[7];  // (V,)
    float* out = (float*)d_out;                    // (B,T,U,V)

    // Projections: 3072 rows x 640 cols, 64x64 tiles -> grid (10, 48)
    proj_kernel<<<dim3(10, 48), 256>>>(enc_h, dec_h, enc_w, enc_b, dec_w, dec_b);
    // Joint GEMM: M=262144 (2048 tiles of 128), N=1024 (8 tiles of 128)
    joint_kernel<<<dim3(8, 2048), 256>>>(dense_w, dense_b, out);
}

// round 4
// speedup vs baseline: 2.8805x; 2.8805x over previous
#include <cuda_runtime.h>
#include <cuda_fp16.h>
#include <cstdint>

// Problem constants
#define BB 8
#define TT 256
#define UU 128
#define HH 512
#define II 640
#define VV 1024

// Scratch (no cudaMalloc allowed)
__device__ float  g_enc_proj[BB * TT * II];   // (2048, 640) fp32
__device__ float  g_dec_proj[BB * UU * II];   // (1024, 640) fp32
__device__ __half g_w_half[VV * II];          // W^T fp16 [v][k]

__device__ __forceinline__ uint32_t smem_u32(const void* p) {
    uint32_t a;
    asm("{ .reg .u64 t; cvta.to.shared.u64 t, %1; cvt.u32.u64 %0, t; }"
        : "=r"(a) : "l"(p));
    return a;
}

// fast tanh: 1 - 2/(exp(2x)+1) -> 2 MUFU ops, rel err ~1e-6, saturates at +-1
__device__ __forceinline__ float tanh_fast(float x) {
    float e = __expf(2.0f * x);
    return 1.0f - __fdividef(2.0f, e + 1.0f);
}

__device__ __forceinline__ void mma16816(float* c,
    uint32_t a0, uint32_t a1, uint32_t a2, uint32_t a3,
    uint32_t b0, uint32_t b1)
{
    asm volatile(
        "mma.sync.aligned.m16n8k16.row.col.f32.f16.f16.f32 "
        "{%0,%1,%2,%3}, {%4,%5,%6,%7}, {%8,%9}, {%0,%1,%2,%3};"
        : "+f"(c[0]), "+f"(c[1]), "+f"(c[2]), "+f"(c[3])
        : "r"(a0), "r"(a1), "r"(a2), "r"(a3), "r"(b0), "r"(b1));
}

__device__ __forceinline__ void cp_async16(uint32_t dst, const void* src) {
    asm volatile("cp.async.ca.shared.global [%0], [%1], 16;"
                 :: "r"(dst), "l"(src) : "memory");
}
#define CP_COMMIT() asm volatile("cp.async.commit_group;" ::: "memory")
#define CP_WAIT0()  asm volatile("cp.async.wait_group 0;" ::: "memory")

// ---------------------------------------------------------------------------
// Kernel 1: enc/dec projections (proven in R2; tiny: 2 GFLOP)
// ---------------------------------------------------------------------------
__global__ __launch_bounds__(256) void proj_kernel(
    const float* __restrict__ enc_h, const float* __restrict__ dec_h,
    const float* __restrict__ enc_w, const float* __restrict__ enc_b,
    const float* __restrict__ dec_w, const float* __restrict__ dec_b)
{
    __shared__ float As[16][68];
    __shared__ float Bs[16][64];

    const int r0 = blockIdx.y * 64;
    const int n0 = blockIdx.x * 64;

    const float* in; const float* w; const float* bias; float* outp;
    if (r0 < BB * TT) {
        in = enc_h + (size_t)r0 * HH; w = enc_w; bias = enc_b;
        outp = g_enc_proj + (size_t)r0 * II;
    } else {
        const int r = r0 - BB * TT;
        in = dec_h + (size_t)r * HH; w = dec_w; bias = dec_b;
        outp = g_dec_proj + (size_t)r * II;
    }

    const int t  = threadIdx.x;
    const int tx = t & 15, ty = t >> 4;
    const int a_row = t >> 2;
    const int a_k4  = (t & 3) * 4;
    const int b_kk  = t >> 4;
    const int b_j4  = (t & 15) * 4;

    float acc[4][4] = {};
    for (int k0 = 0; k0 < HH; k0 += 16) {
        float4 av = *(const float4*)(in + (size_t)a_row * HH + k0 + a_k4);
        As[a_k4 + 0][a_row] = av.x;
        As[a_k4 + 1][a_row] = av.y;
        As[a_k4 + 2][a_row] = av.z;
        As[a_k4 + 3][a_row] = av.w;
        *(float4*)&Bs[b_kk][b_j4] =
            *(const float4*)(w + (size_t)(k0 + b_kk) * II + n0 + b_j4);
        __syncthreads();
        #pragma unroll
        for (int kk = 0; kk < 16; kk++) {
            float4 a4 = *(const float4*)&As[kk][ty * 4];
            float4 b4 = *(const float4*)&Bs[kk][tx * 4];
            float a[4] = {a4.x, a4.y, a4.z, a4.w};
            float bw[4] = {b4.x, b4.y, b4.z, b4.w};
            #pragma unroll
            for (int i = 0; i < 4; i++)
                #pragma unroll
                for (int j = 0; j < 4; j++)
                    acc[i][j] = fmaf(a[i], bw[j], acc[i][j]);
        }
        __syncthreads();
    }
    float4 bv = *(const float4*)(bias + n0 + tx * 4);
    float bb[4] = {bv.x, bv.y, bv.z, bv.w};
    #pragma unroll
    for (int i = 0; i < 4; i++) {
        float4 o;
        o.x = acc[i][0] + bb[0]; o.y = acc[i][1] + bb[1];
        o.z = acc[i][2] + bb[2]; o.w = acc[i][3] + bb[3];
        *(float4*)(outp + (size_t)(ty * 4 + i) * II + n0 + tx * 4) = o;
    }
}

// ---------------------------------------------------------------------------
// Kernel 2: dense_w (640x1024 [k][v]) -> transposed fp16 [v][k]
// ---------------------------------------------------------------------------
__global__ __launch_bounds__(256) void wsplit_kernel(const float* __restrict__ W) {
    int idx = blockIdx.x * 256 + threadIdx.x;   // 0..655359
    int k = idx >> 10;
    int v = idx & 1023;
    g_w_half[(size_t)v * II + k] = __float2half(W[idx]);
}

// ---------------------------------------------------------------------------
// Kernel 3: fused joint GEMM via HMMA mma.sync m16n8k16 fp16.
// BM=128 (=U: one bt per CTA row-tile), BN=256, BK=32, 8 warps (2x4),
// warp tile 64x64, double-buffered smem, cp.async for W, tanh fused in
// the A-producer. Joint tensor never touches GMEM.
// ---------------------------------------------------------------------------
#define A_BYTES 10240             // 128 rows * 80B (32 fp16 + 16B pad)
#define B_BYTES 20480             // 256 rows * 80B
#define BUF_BYTES (A_BYTES + B_BYTES)
#define DYN_SMEM (2 * BUF_BYTES)  // 61440
#define NCHUNK 20                 // 640 / 32

__global__ __launch_bounds__(256, 1) void joint_mma_kernel(
    const float* __restrict__ dense_b, float* __restrict__ out)
{
    extern __shared__ __align__(16) char smem[];
    const int tid  = threadIdx.x;
    const int lane = tid & 31;
    const int wid  = tid >> 5;
    const int warp_m = wid >> 2;   // 0..1
    const int warp_n = wid & 3;    // 0..3

    const int n0 = blockIdx.x * 256;
    const int bt = blockIdx.y;
    const int b  = bt >> 8;

    const float* __restrict__ encp = g_enc_proj + (size_t)bt * II;
    const float* __restrict__ decp = g_dec_proj + (size_t)(b * UU) * II;

    float acc[4][8][4];
    #pragma unroll
    for (int i = 0; i < 4; i++)
        #pragma unroll
        for (int j = 0; j < 8; j++)
            #pragma unroll
            for (int l = 0; l < 4; l++) acc[i][j][l] = 0.0f;

    const int a_row  = tid & 127;   // A producer: row (u)
    const int a_half = tid >> 7;    // k-half (0: k0..15, 1: k16..31)

    // ---- A producer: tanh(enc+dec) -> fp16, 80B-padded rows ----
    auto produceA = [&](int k0, char* Ab) {
        const int kc = k0 + a_half * 16;
        const float* dp = decp + (size_t)a_row * II + kc;
        const float* ep = encp + kc;
        float s[16];
        #pragma unroll
        for (int q = 0; q < 4; q++) {
            float4 d = *(const float4*)(dp + q * 4);
            float4 e = *(const float4*)(ep + q * 4);
            s[q * 4 + 0] = tanh_fast(d.x + e.x);
            s[q * 4 + 1] = tanh_fast(d.y + e.y);
            s[q * 4 + 2] = tanh_fast(d.z + e.z);
            s[q * 4 + 3] = tanh_fast(d.w + e.w);
        }
        uint32_t h[8];
        #pragma unroll
        for (int q = 0; q < 8; q++) {
            __half2 hh = __floats2half2_rn(s[2 * q], s[2 * q + 1]);
            h[q] = *reinterpret_cast<uint32_t*>(&hh);
        }
        uint4* dst = (uint4*)(Ab + a_row * 80 + a_half * 32);
        dst[0] = make_uint4(h[0], h[1], h[2], h[3]);
        dst[1] = make_uint4(h[4], h[5], h[6], h[7]);
    };

    // ---- B producer: cp.async W^T fp16 slice (256 n-rows x 32 k) ----
    auto produceB = [&](int k0, uint32_t Bb_u32) {
        #pragma unroll
        for (int j = 0; j < 4; j++) {
            int idx = tid + j * 256;     // 0..1023
            int nl = idx >> 2;
            int q  = idx & 3;
            const __half* src = g_w_half + (size_t)(n0 + nl) * II + k0 + q * 8;
            cp_async16(Bb_u32 + nl * 80 + q * 16, src);
        }
    };

    // ---- MMA consumer: 2 k16-steps, 4 m-tiles x 8 n-tiles per warp ----
    auto mmaStep = [&](const char* Ab, const char* Bb) {
        #pragma unroll
        for (int ks = 0; ks < 2; ks++) {
            const int kk = ks * 16 + (lane & 3) * 2;
            uint32_t bf0[8], bf1[8];
            #pragma unroll
            for (int nt = 0; nt < 8; nt++) {
                int nl = warp_n * 64 + nt * 8 + (lane >> 2);
                const char* p = Bb + nl * 80 + kk * 2;
                bf0[nt] = *(const uint32_t*)p;
                bf1[nt] = *(const uint32_t*)(p + 16);
            }
            #pragma unroll
            for (int mt = 0; mt < 4; mt++) {
                int r = warp_m * 64 + mt * 16 + (lane >> 2);
                const char* p = Ab + r * 80 + kk * 2;
                uint32_t a0 = *(const uint32_t*)p;
                uint32_t a1 = *(const uint32_t*)(p + 8 * 80);
                uint32_t a2 = *(const uint32_t*)(p + 16);
                uint32_t a3 = *(const uint32_t*)(p + 8 * 80 + 16);
                #pragma unroll
                for (int nt = 0; nt < 8; nt++)
                    mma16816(acc[mt][nt], a0, a1, a2, a3, bf0[nt], bf1[nt]);
            }
        }
    };

    const uint32_t smb = smem_u32(smem);

    // Prologue: fill buffer 0 with chunk 0
    produceB(0, smb + A_BYTES);
    produceA(0, smem);
    CP_COMMIT();
    CP_WAIT0();
    __syncthreads();

    #pragma unroll 1
    for (int ic = 0; ic < NCHUNK; ic++) {
        const int cur = ic & 1;
        char* Acur = smem + cur * BUF_BYTES;
        if (ic + 1 < NCHUNK) {
            const int nxt = cur ^ 1;
            produceB((ic + 1) * 32, smb + nxt * BUF_BYTES + A_BYTES);
            produceA((ic + 1) * 32, smem + nxt * BUF_BYTES);
            CP_COMMIT();
        }
        mmaStep(Acur, Acur + A_BYTES);
        CP_WAIT0();
        __syncthreads();
    }

    // ---- epilogue: + bias, float2 stores (32B/row per warp quad) ----
    #pragma unroll
    for (int mt = 0; mt < 4; mt++) {
        int r0 = bt * 128 + warp_m * 64 + mt * 16 + (lane >> 2);
        float* o0 = out + (size_t)r0 * VV;
        #pragma unroll
        for (int nt = 0; nt < 8; nt++) {
            int col = n0 + warp_n * 64 + nt * 8 + (lane & 3) * 2;
            float2 bb = *(const float2*)(dense_b + col);
            float2 v0 = make_float2(acc[mt][nt][0] + bb.x, acc[mt][nt][1] + bb.y);
            float2 v1 = make_float2(acc[mt][nt][2] + bb.x, acc[mt][nt][3] + bb.y);
            *(float2*)(o0 + col) = v0;
            *(float2*)(o0 + (size_t)8 * VV + col) = v1;
        }
    }
}

// ---------------------------------------------------------------------------
extern "C" void kernel_launch(void* const* d_in, const int* in_sizes, int n_in,
                              void* d_out, int out_size) {
    const float* enc_h   = (const float*)d_in[0];
    const float* dec_h   = (const float*)d_in[1];
    const float* enc_w   = (const float*)d_in[2];
    const float* enc_b   = (const float*)d_in[3];
    const float* dec_w   = (const float*)d_in[4];
    const float* dec_b   = (const float*)d_in[5];
    const float* dense_w = (const float*)d_in[6];
    const float* dense_b = (const float*)d_in[7];
    float* out = (float*)d_out;

    static bool attr_set = false;
    if (!attr_set) {
        cudaFuncSetAttribute(joint_mma_kernel,
                             cudaFuncAttributeMaxDynamicSharedMemorySize, DYN_SMEM);
        attr_set = true;
    }

    proj_kernel<<<dim3(10, 48), 256>>>(enc_h, dec_h, enc_w, enc_b, dec_w, dec_b);
    wsplit_kernel<<<(II * VV) / 256, 256>>>(dense_w);
    // 2048 bt-tiles x 4 n-tiles of 256
    joint_mma_kernel<<<dim3(4, 2048), 256, DYN_SMEM>>>(dense_b, out);
}

// round 5
// speedup vs baseline: 3.9199x; 1.3609x over previous
#include <cuda_runtime.h>
#include <cuda_fp16.h>
#include <cstdint>

// Problem constants
#define BB 8
#define TT 256
#define UU 128
#define HH 512
#define II 640
#define VV 1024

// Scratch (no cudaMalloc allowed)
__device__ float  g_enc_proj[BB * TT * II];   // (2048, 640) fp32
__device__ float  g_dec_proj[BB * UU * II];   // (1024, 640) fp32
__device__ __half g_w_half[VV * II];          // W^T fp16 [v][k]

__device__ __forceinline__ uint32_t smem_u32(const void* p) {
    uint32_t a;
    asm("{ .reg .u64 t; cvta.to.shared.u64 t, %1; cvt.u32.u64 %0, t; }"
        : "=r"(a) : "l"(p));
    return a;
}

// fast tanh: 1 - 2/(exp(2x)+1) -> 2 MUFU ops, rel err ~1e-6, saturates at +-1
__device__ __forceinline__ float tanh_fast(float x) {
    float e = __expf(2.0f * x);
    return 1.0f - __fdividef(2.0f, e + 1.0f);
}

__device__ __forceinline__ void mma16816(float* c,
    uint32_t a0, uint32_t a1, uint32_t a2, uint32_t a3,
    uint32_t b0, uint32_t b1)
{
    asm volatile(
        "mma.sync.aligned.m16n8k16.row.col.f32.f16.f16.f32 "
        "{%0,%1,%2,%3}, {%4,%5,%6,%7}, {%8,%9}, {%0,%1,%2,%3};"
        : "+f"(c[0]), "+f"(c[1]), "+f"(c[2]), "+f"(c[3])
        : "r"(a0), "r"(a1), "r"(a2), "r"(a3), "r"(b0), "r"(b1));
}

__device__ __forceinline__ void cp_async16(uint32_t dst, const void* src) {
    asm volatile("cp.async.ca.shared.global [%0], [%1], 16;"
                 :: "r"(dst), "l"(src) : "memory");
}
#define CP_COMMIT() asm volatile("cp.async.commit_group;" ::: "memory")
#define CP_WAIT0()  asm volatile("cp.async.wait_group 0;" ::: "memory")

// ---------------------------------------------------------------------------
// Kernel 1: enc/dec projections (tiny: 2 GFLOP)
// ---------------------------------------------------------------------------
__global__ __launch_bounds__(256) void proj_kernel(
    const float* __restrict__ enc_h, const float* __restrict__ dec_h,
    const float* __restrict__ enc_w, const float* __restrict__ enc_b,
    const float* __restrict__ dec_w, const float* __restrict__ dec_b)
{
    __shared__ float As[16][68];
    __shared__ float Bs[16][64];

    const int r0 = blockIdx.y * 64;
    const int n0 = blockIdx.x * 64;

    const float* in; const float* w; const float* bias; float* outp;
    if (r0 < BB * TT) {
        in = enc_h + (size_t)r0 * HH; w = enc_w; bias = enc_b;
        outp = g_enc_proj + (size_t)r0 * II;
    } else {
        const int r = r0 - BB * TT;
        in = dec_h + (size_t)r * HH; w = dec_w; bias = dec_b;
        outp = g_dec_proj + (size_t)r * II;
    }

    const int t  = threadIdx.x;
    const int tx = t & 15, ty = t >> 4;
    const int a_row = t >> 2;
    const int a_k4  = (t & 3) * 4;
    const int b_kk  = t >> 4;
    const int b_j4  = (t & 15) * 4;

    float acc[4][4] = {};
    for (int k0 = 0; k0 < HH; k0 += 16) {
        float4 av = *(const float4*)(in + (size_t)a_row * HH + k0 + a_k4);
        As[a_k4 + 0][a_row] = av.x;
        As[a_k4 + 1][a_row] = av.y;
        As[a_k4 + 2][a_row] = av.z;
        As[a_k4 + 3][a_row] = av.w;
        *(float4*)&Bs[b_kk][b_j4] =
            *(const float4*)(w + (size_t)(k0 + b_kk) * II + n0 + b_j4);
        __syncthreads();
        #pragma unroll
        for (int kk = 0; kk < 16; kk++) {
            float4 a4 = *(const float4*)&As[kk][ty * 4];
            float4 b4 = *(const float4*)&Bs[kk][tx * 4];
            float a[4] = {a4.x, a4.y, a4.z, a4.w};
            float bw[4] = {b4.x, b4.y, b4.z, b4.w};
            #pragma unroll
            for (int i = 0; i < 4; i++)
                #pragma unroll
                for (int j = 0; j < 4; j++)
                    acc[i][j] = fmaf(a[i], bw[j], acc[i][j]);
        }
        __syncthreads();
    }
    float4 bv = *(const float4*)(bias + n0 + tx * 4);
    float bb[4] = {bv.x, bv.y, bv.z, bv.w};
    #pragma unroll
    for (int i = 0; i < 4; i++) {
        float4 o;
        o.x = acc[i][0] + bb[0]; o.y = acc[i][1] + bb[1];
        o.z = acc[i][2] + bb[2]; o.w = acc[i][3] + bb[3];
        *(float4*)(outp + (size_t)(ty * 4 + i) * II + n0 + tx * 4) = o;
    }
}

// ---------------------------------------------------------------------------
// Kernel 2: dense_w (640x1024 [k][v]) -> transposed fp16 [v][k]
// ---------------------------------------------------------------------------
__global__ __launch_bounds__(256) void wsplit_kernel(const float* __restrict__ W) {
    int idx = blockIdx.x * 256 + threadIdx.x;   // 0..655359
    int k = idx >> 10;
    int v = idx & 1023;
    g_w_half[(size_t)v * II + k] = __float2half(W[idx]);
}

// ---------------------------------------------------------------------------
// Kernel 3: fused joint GEMM. One CTA per bt, full V=1024 coverage.
// Phase 1: A panel = tanh(enc+dec) fp16, 128x640, resident in smem (162KB).
// Mainloop: pure GEMM — 4 n-tiles (256) x 20 k-chunks (BK=32), B via
// cp.async double buffer from L2-resident W^T. 512 thr / 16 warps, warp
// tile 32x64 (acc 64 regs). No global-A loads, no MUFU in mainloop.
// ---------------------------------------------------------------------------
#define A_STRIDE 1296                 // 640*2 + 16B pad (conflict-free: bank=4r+j)
#define A_PANEL  (128 * A_STRIDE)     // 165888
#define B_STRIDE 80                   // 32*2 + 16B pad
#define B_CHUNK  (256 * B_STRIDE)     // 20480
#define DYN_SMEM (A_PANEL + 2 * B_CHUNK)  // 206848
#define NCHUNK   20

__global__ __launch_bounds__(512, 1) void joint_mma_kernel(
    const float* __restrict__ dense_b, float* __restrict__ out)
{
    extern __shared__ __align__(16) char smem[];
    char* Apanel = smem;
    char* Bbuf   = smem + A_PANEL;
    const uint32_t smb_B = smem_u32(smem) + A_PANEL;

    const int tid  = threadIdx.x;
    const int lane = tid & 31;
    const int wid  = tid >> 5;
    const int warp_m = wid & 3;    // 0..3 (M quarters of 32)
    const int warp_n = wid >> 2;   // 0..3 (N quarters of 64 within 256-tile)

    const int bt = blockIdx.x;
    const int b  = bt >> 8;

    const float* __restrict__ encp = g_enc_proj + (size_t)bt * II;
    const float* __restrict__ decp = g_dec_proj + (size_t)(b * UU) * II;

    // ---- Phase 1: build full A panel in smem (tanh + fp16 pack) ----
    {
        const int row = tid >> 2;          // 0..127
        const int kq  = tid & 3;           // 4 threads per row
        const float* dp = decp + (size_t)row * II;
        #pragma unroll 1
        for (int seg = 0; seg < 10; seg++) {
            const int k = seg * 64 + kq * 16;
            float s[16];
            #pragma unroll
            for (int q = 0; q < 4; q++) {
                float4 d = *(const float4*)(dp + k + q * 4);
                float4 e = *(const float4*)(encp + k + q * 4);
                s[q * 4 + 0] = tanh_fast(d.x + e.x);
                s[q * 4 + 1] = tanh_fast(d.y + e.y);
                s[q * 4 + 2] = tanh_fast(d.z + e.z);
                s[q * 4 + 3] = tanh_fast(d.w + e.w);
            }
            uint32_t h[8];
            #pragma unroll
            for (int q = 0; q < 8; q++) {
                __half2 hh = __floats2half2_rn(s[2 * q], s[2 * q + 1]);
                h[q] = *reinterpret_cast<uint32_t*>(&hh);
            }
            uint4* dst = (uint4*)(Apanel + row * A_STRIDE + k * 2);
            dst[0] = make_uint4(h[0], h[1], h[2], h[3]);
            dst[1] = make_uint4(h[4], h[5], h[6], h[7]);
        }
    }
    __syncthreads();

    // ---- B producer: 256 n-rows x 32 k fp16 per chunk (64B data + 16B pad) ----
    auto produceB = [&](int n0, int k0, uint32_t dst) {
        #pragma unroll
        for (int j = 0; j < 2; j++) {
            int idx = tid + j * 512;       // 0..1023
            int nl = idx >> 2;
            int q  = idx & 3;
            const __half* src = g_w_half + (size_t)(n0 + nl) * II + k0 + q * 8;
            cp_async16(dst + nl * B_STRIDE + q * 16, src);
        }
    };

    float acc[2][8][4];

    #pragma unroll 1
    for (int nt4 = 0; nt4 < 4; nt4++) {
        const int n0 = nt4 * 256;

        #pragma unroll
        for (int i = 0; i < 2; i++)
            #pragma unroll
            for (int j = 0; j < 8; j++)
                #pragma unroll
                for (int l = 0; l < 4; l++) acc[i][j][l] = 0.0f;

        // prologue: chunk 0 into buf 0
        produceB(n0, 0, smb_B);
        CP_COMMIT();
        CP_WAIT0();
        __syncthreads();

        #pragma unroll 1
        for (int ic = 0; ic < NCHUNK; ic++) {
            const int cur = ic & 1;
            if (ic + 1 < NCHUNK) {
                produceB(n0, (ic + 1) * 32, smb_B + (cur ^ 1) * B_CHUNK);
                CP_COMMIT();
            }
            // ---- MMA on current chunk ----
            const char* Bb = Bbuf + cur * B_CHUNK;
            #pragma unroll
            for (int ks = 0; ks < 2; ks++) {
                const int kk = ks * 16 + (lane & 3) * 2;   // k within chunk
                uint32_t bf0[8], bf1[8];
                #pragma unroll
                for (int nt = 0; nt < 8; nt++) {
                    const char* p = Bb + (warp_n * 64 + nt * 8 + (lane >> 2)) * B_STRIDE + kk * 2;
                    bf0[nt] = *(const uint32_t*)p;
                    bf1[nt] = *(const uint32_t*)(p + 16);
                }
                #pragma unroll
                for (int mt = 0; mt < 2; mt++) {
                    const int r = warp_m * 32 + mt * 16 + (lane >> 2);
                    const char* p = Apanel + r * A_STRIDE + (ic * 32 + kk) * 2;
                    uint32_t a0 = *(const uint32_t*)p;
                    uint32_t a1 = *(const uint32_t*)(p + 8 * A_STRIDE);
                    uint32_t a2 = *(const uint32_t*)(p + 16);
                    uint32_t a3 = *(const uint32_t*)(p + 8 * A_STRIDE + 16);
                    #pragma unroll
                    for (int nt = 0; nt < 8; nt++)
                        mma16816(acc[mt][nt], a0, a1, a2, a3, bf0[nt], bf1[nt]);
                }
            }
            CP_WAIT0();
            __syncthreads();
        }

        // ---- epilogue for this n-tile: +bias, float2 stores ----
        #pragma unroll
        for (int mt = 0; mt < 2; mt++) {
            const int r = warp_m * 32 + mt * 16 + (lane >> 2);
            float* o0 = out + ((size_t)bt * 128 + r) * VV;
            #pragma unroll
            for (int nt = 0; nt < 8; nt++) {
                const int col = n0 + warp_n * 64 + nt * 8 + (lane & 3) * 2;
                float2 bb = *(const float2*)(dense_b + col);
                float2 v0 = make_float2(acc[mt][nt][0] + bb.x, acc[mt][nt][1] + bb.y);
                float2 v1 = make_float2(acc[mt][nt][2] + bb.x, acc[mt][nt][3] + bb.y);
                *(float2*)(o0 + col) = v0;
                *(float2*)(o0 + (size_t)8 * VV + col) = v1;
            }
        }
    }
}

// ---------------------------------------------------------------------------
extern "C" void kernel_launch(void* const* d_in, const int* in_sizes, int n_in,
                              void* d_out, int out_size) {
    const float* enc_h   = (const float*)d_in[0];
    const float* dec_h   = (const float*)d_in[1];
    const float* enc_w   = (const float*)d_in[2];
    const float* enc_b   = (const float*)d_in[3];
    const float* dec_w   = (const float*)d_in[4];
    const float* dec_b   = (const float*)d_in[5];
    const float* dense_w = (const float*)d_in[6];
    const float* dense_b = (const float*)d_in[7];
    float* out = (float*)d_out;

    static bool attr_set = false;
    if (!attr_set) {
        cudaFuncSetAttribute(joint_mma_kernel,
                             cudaFuncAttributeMaxDynamicSharedMemorySize, DYN_SMEM);
        attr_set = true;
    }

    proj_kernel<<<dim3(10, 48), 256>>>(enc_h, dec_h, enc_w, enc_b, dec_w, dec_b);
    wsplit_kernel<<<(II * VV) / 256, 256>>>(dense_w);
    // one CTA per bt; each covers full V
    joint_mma_kernel<<<2048, 512, DYN_SMEM>>>(dense_b, out);
}

// round 6
// speedup vs baseline: 4.5987x; 1.1732x over previous
#include <cuda_runtime.h>
#include <cuda_fp16.h>
#include <cstdint>

// Problem constants
#define BB 8
#define TT 256
#define UU 128
#define HH 512
#define II 640
#define VV 1024

// Scratch (no cudaMalloc allowed)
__device__ float  g_enc_proj[BB * TT * II];   // (2048, 640) fp32
__device__ float  g_dec_proj[BB * UU * II];   // (1024, 640) fp32
__device__ __half g_w_half[VV * II];          // W^T fp16 [v][k]

__device__ __forceinline__ uint32_t smem_u32(const void* p) {
    uint32_t a;
    asm("{ .reg .u64 t; cvta.to.shared.u64 t, %1; cvt.u32.u64 %0, t; }"
        : "=r"(a) : "l"(p));
    return a;
}

// fast tanh: 1 - 2/(exp(2x)+1) -> 2 MUFU ops, rel err ~1e-6, saturates at +-1
__device__ __forceinline__ float tanh_fast(float x) {
    float e = __expf(2.0f * x);
    return 1.0f - __fdividef(2.0f, e + 1.0f);
}

__device__ __forceinline__ void mma16816(float* c,
    uint32_t a0, uint32_t a1, uint32_t a2, uint32_t a3,
    uint32_t b0, uint32_t b1)
{
    asm volatile(
        "mma.sync.aligned.m16n8k16.row.col.f32.f16.f16.f32 "
        "{%0,%1,%2,%3}, {%4,%5,%6,%7}, {%8,%9}, {%0,%1,%2,%3};"
        : "+f"(c[0]), "+f"(c[1]), "+f"(c[2]), "+f"(c[3])
        : "r"(a0), "r"(a1), "r"(a2), "r"(a3), "r"(b0), "r"(b1));
}

__device__ __forceinline__ void ldsm4(uint32_t* r, uint32_t addr) {
    asm volatile("ldmatrix.sync.aligned.m8n8.x4.shared.b16 {%0,%1,%2,%3}, [%4];"
        : "=r"(r[0]), "=r"(r[1]), "=r"(r[2]), "=r"(r[3]) : "r"(addr));
}

__device__ __forceinline__ void cp_async16(uint32_t dst, const void* src) {
    asm volatile("cp.async.ca.shared.global [%0], [%1], 16;"
                 :: "r"(dst), "l"(src) : "memory");
}
#define CP_COMMIT() asm volatile("cp.async.commit_group;" ::: "memory")
#define CP_WAIT1()  asm volatile("cp.async.wait_group 1;" ::: "memory")

// ---------------------------------------------------------------------------
// Kernel 1: enc/dec projections (tiny: 2 GFLOP)
// ---------------------------------------------------------------------------
__global__ __launch_bounds__(256) void proj_kernel(
    const float* __restrict__ enc_h, const float* __restrict__ dec_h,
    const float* __restrict__ enc_w, const float* __restrict__ enc_b,
    const float* __restrict__ dec_w, const float* __restrict__ dec_b)
{
    __shared__ float As[16][68];
    __shared__ float Bs[16][64];

    const int r0 = blockIdx.y * 64;
    const int n0 = blockIdx.x * 64;

    const float* in; const float* w; const float* bias; float* outp;
    if (r0 < BB * TT) {
        in = enc_h + (size_t)r0 * HH; w = enc_w; bias = enc_b;
        outp = g_enc_proj + (size_t)r0 * II;
    } else {
        const int r = r0 - BB * TT;
        in = dec_h + (size_t)r * HH; w = dec_w; bias = dec_b;
        outp = g_dec_proj + (size_t)r * II;
    }

    const int t  = threadIdx.x;
    const int tx = t & 15, ty = t >> 4;
    const int a_row = t >> 2;
    const int a_k4  = (t & 3) * 4;
    const int b_kk  = t >> 4;
    const int b_j4  = (t & 15) * 4;

    float acc[4][4] = {};
    for (int k0 = 0; k0 < HH; k0 += 16) {
        float4 av = *(const float4*)(in + (size_t)a_row * HH + k0 + a_k4);
        As[a_k4 + 0][a_row] = av.x;
        As[a_k4 + 1][a_row] = av.y;
        As[a_k4 + 2][a_row] = av.z;
        As[a_k4 + 3][a_row] = av.w;
        *(float4*)&Bs[b_kk][b_j4] =
            *(const float4*)(w + (size_t)(k0 + b_kk) * II + n0 + b_j4);
        __syncthreads();
        #pragma unroll
        for (int kk = 0; kk < 16; kk++) {
            float4 a4 = *(const float4*)&As[kk][ty * 4];
            float4 b4 = *(const float4*)&Bs[kk][tx * 4];
            float a[4] = {a4.x, a4.y, a4.z, a4.w};
            float bw[4] = {b4.x, b4.y, b4.z, b4.w};
            #pragma unroll
            for (int i = 0; i < 4; i++)
                #pragma unroll
                for (int j = 0; j < 4; j++)
                    acc[i][j] = fmaf(a[i], bw[j], acc[i][j]);
        }
        __syncthreads();
    }
    float4 bv = *(const float4*)(bias + n0 + tx * 4);
    float bb[4] = {bv.x, bv.y, bv.z, bv.w};
    #pragma unroll
    for (int i = 0; i < 4; i++) {
        float4 o;
        o.x = acc[i][0] + bb[0]; o.y = acc[i][1] + bb[1];
        o.z = acc[i][2] + bb[2]; o.w = acc[i][3] + bb[3];
        *(float4*)(outp + (size_t)(ty * 4 + i) * II + n0 + tx * 4) = o;
    }
}

// ---------------------------------------------------------------------------
// Kernel 2: dense_w (640x1024 [k][v]) -> transposed fp16 [v][k]
// ---------------------------------------------------------------------------
__global__ __launch_bounds__(256) void wsplit_kernel(const float* __restrict__ W) {
    int idx = blockIdx.x * 256 + threadIdx.x;   // 0..655359
    int k = idx >> 10;
    int v = idx & 1023;
    g_w_half[(size_t)v * II + k] = __float2half(W[idx]);
}

// ---------------------------------------------------------------------------
// Kernel 3: fused joint GEMM. One CTA per bt, full V=1024.
// Phase 1: A panel 128x640 fp16 resident in smem (162KB).
// Mainloop: flat 80-chunk loop (4 n-tiles x 20 k-chunks), B via 3-stage
// cp.async pipeline, ldmatrix.x4 fragment loads, 1 barrier per chunk.
// ---------------------------------------------------------------------------
#define A_STRIDE 1296                 // 640*2 + 16B pad (324 words, %32 = 4)
#define A_PANEL  (128 * A_STRIDE)     // 165888
#define B_STRIDE 80                   // 32*2 + 16B pad (20 words)
#define B_CHUNK  (256 * B_STRIDE)     // 20480
#define NSTAGE   3
#define DYN_SMEM (A_PANEL + NSTAGE * B_CHUNK)  // 227328
#define NCHUNK   80                   // 4 n-tiles * 20 k-chunks

__global__ __launch_bounds__(512, 1) void joint_mma_kernel(
    const float* __restrict__ dense_b, float* __restrict__ out)
{
    extern __shared__ __align__(16) char smem[];
    char* Apanel = smem;
    const uint32_t smb   = smem_u32(smem);
    const uint32_t smb_B = smb + A_PANEL;

    const int tid  = threadIdx.x;
    const int lane = tid & 31;
    const int wid  = tid >> 5;
    const int warp_m = wid & 3;    // 0..3 (M quarters of 32)
    const int warp_n = wid >> 2;   // 0..3 (N quarters of 64 within 256-tile)

    const int bt = blockIdx.x;
    const int b  = bt >> 8;

    const float* __restrict__ encp = g_enc_proj + (size_t)bt * II;
    const float* __restrict__ decp = g_dec_proj + (size_t)(b * UU) * II;

    // ---- Phase 1: build full A panel in smem (tanh + fp16 pack) ----
    {
        const int row = tid >> 2;          // 0..127
        const int kq  = tid & 3;           // 4 threads per row
        const float* dp = decp + (size_t)row * II;
        #pragma unroll 1
        for (int seg = 0; seg < 10; seg++) {
            const int k = seg * 64 + kq * 16;
            float s[16];
            #pragma unroll
            for (int q = 0; q < 4; q++) {
                float4 d = *(const float4*)(dp + k + q * 4);
                float4 e = *(const float4*)(encp + k + q * 4);
                s[q * 4 + 0] = tanh_fast(d.x + e.x);
                s[q * 4 + 1] = tanh_fast(d.y + e.y);
                s[q * 4 + 2] = tanh_fast(d.z + e.z);
                s[q * 4 + 3] = tanh_fast(d.w + e.w);
            }
            uint32_t h[8];
            #pragma unroll
            for (int q = 0; q < 8; q++) {
                __half2 hh = __floats2half2_rn(s[2 * q], s[2 * q + 1]);
                h[q] = *reinterpret_cast<uint32_t*>(&hh);
            }
            uint4* dst = (uint4*)(Apanel + row * A_STRIDE + k * 2);
            dst[0] = make_uint4(h[0], h[1], h[2], h[3]);
            dst[1] = make_uint4(h[4], h[5], h[6], h[7]);
        }
    }

    // ---- B producer for flat chunk c: n0=(c/20)*256, k0=(c%20)*32 ----
    auto produceB = [&](int c, uint32_t dst) {
        const int n0 = (c / 20) * 256;
        const int k0 = (c % 20) * 32;
        #pragma unroll
        for (int j = 0; j < 2; j++) {
            int idx = tid + j * 512;       // 0..1023
            int nl = idx >> 2;
            int q  = idx & 3;
            const __half* src = g_w_half + (size_t)(n0 + nl) * II + k0 + q * 8;
            cp_async16(dst + nl * B_STRIDE + q * 16, src);
        }
    };

    // ---- per-lane ldmatrix base offsets ----
    // A: lane -> row (lane&15), k-half (lane>>4)*16B; per mt +16 rows.
    const uint32_t A_lane = smb + (uint32_t)(warp_m * 32 + (lane & 15)) * A_STRIDE
                                + (uint32_t)(lane >> 4) * 16;
    // B: matrices (nt,klo),(nt,khi),(nt+1,klo),(nt+1,khi):
    // row = base + ((lane>>4)<<3) + (lane&7); koff = ((lane>>3)&1)*16.
    const uint32_t B_lane = (uint32_t)(warp_n * 64 + ((lane >> 4) << 3) + (lane & 7)) * B_STRIDE
                          + (uint32_t)((lane >> 3) & 1) * 16;

    float acc[2][8][4];
    #pragma unroll
    for (int i = 0; i < 2; i++)
        #pragma unroll
        for (int j = 0; j < 8; j++)
            #pragma unroll
            for (int l = 0; l < 4; l++) acc[i][j][l] = 0.0f;

    __syncthreads();   // A panel ready

    // Prologue: chunks 0,1 into stages 0,1
    produceB(0, smb_B);
    CP_COMMIT();
    produceB(1, smb_B + B_CHUNK);
    CP_COMMIT();
    CP_WAIT1();        // chunk 0 landed
    __syncthreads();

    #pragma unroll 1
    for (int c = 0; c < NCHUNK; c++) {
        const int stage = c % NSTAGE;
        // prefetch chunk c+2 into stage (c+2)%NSTAGE (freed by last barrier)
        if (c + 2 < NCHUNK) produceB(c + 2, smb_B + ((c + 2) % NSTAGE) * B_CHUNK);
        CP_COMMIT();   // uniform group accounting (empty group near tail)

        // ---- MMA on chunk c ----
        const uint32_t Bbase = smb_B + stage * B_CHUNK + B_lane;
        const uint32_t Abase = A_lane + (uint32_t)(c % 20) * 64;
        #pragma unroll
        for (int ks = 0; ks < 2; ks++) {
            uint32_t a0[4], a1[4];
            ldsm4(a0, Abase + ks * 32);                      // mt 0
            ldsm4(a1, Abase + ks * 32 + 16 * A_STRIDE);      // mt 1
            uint32_t bf[4][4];
            #pragma unroll
            for (int ntp = 0; ntp < 4; ntp++)
                ldsm4(bf[ntp], Bbase + ntp * (16 * B_STRIDE) + ks * 32);
            #pragma unroll
            for (int ntp = 0; ntp < 4; ntp++) {
                mma16816(acc[0][2 * ntp + 0], a0[0], a0[1], a0[2], a0[3], bf[ntp][0], bf[ntp][1]);
                mma16816(acc[0][2 * ntp + 1], a0[0], a0[1], a0[2], a0[3], bf[ntp][2], bf[ntp][3]);
                mma16816(acc[1][2 * ntp + 0], a1[0], a1[1], a1[2], a1[3], bf[ntp][0], bf[ntp][1]);
                mma16816(acc[1][2 * ntp + 1], a1[0], a1[1], a1[2], a1[3], bf[ntp][2], bf[ntp][3]);
            }
        }

        // ---- epilogue at n-tile boundary ----
        if ((c % 20) == 19) {
            const int n0 = (c / 20) * 256;
            #pragma unroll
            for (int mt = 0; mt < 2; mt++) {
                const int r = warp_m * 32 + mt * 16 + (lane >> 2);
                float* o0 = out + ((size_t)bt * 128 + r) * VV;
                #pragma unroll
                for (int nt = 0; nt < 8; nt++) {
                    const int col = n0 + warp_n * 64 + nt * 8 + (lane & 3) * 2;
                    float2 bb = *(const float2*)(dense_b + col);
                    float2 v0 = make_float2(acc[mt][nt][0] + bb.x, acc[mt][nt][1] + bb.y);
                    float2 v1 = make_float2(acc[mt][nt][2] + bb.x, acc[mt][nt][3] + bb.y);
                    *(float2*)(o0 + col) = v0;
                    *(float2*)(o0 + (size_t)8 * VV + col) = v1;
                    #pragma unroll
                    for (int l = 0; l < 4; l++) acc[mt][nt][l] = 0.0f;
                }
            }
        }

        CP_WAIT1();      // chunk c+1 landed (all groups except newest)
        __syncthreads(); // publish + protect stage reuse
    }
}

// ---------------------------------------------------------------------------
extern "C" void kernel_launch(void* const* d_in, const int* in_sizes, int n_in,
                              void* d_out, int out_size) {
    const float* enc_h   = (const float*)d_in[0];
    const float* dec_h   = (const float*)d_in[1];
    const float* enc_w   = (const float*)d_in[2];
    const float* enc_b   = (const float*)d_in[3];
    const float* dec_w   = (const float*)d_in[4];
    const float* dec_b   = (const float*)d_in[5];
    const float* dense_w = (const float*)d_in[6];
    const float* dense_b = (const float*)d_in[7];
    float* out = (float*)d_out;

    static bool attr_set = false;
    if (!attr_set) {
        cudaFuncSetAttribute(joint_mma_kernel,
                             cudaFuncAttributeMaxDynamicSharedMemorySize, DYN_SMEM);
        attr_set = true;
    }

    proj_kernel<<<dim3(10, 48), 256>>>(enc_h, dec_h, enc_w, enc_b, dec_w, dec_b);
    wsplit_kernel<<<(II * VV) / 256, 256>>>(dense_w);
    // one CTA per bt; each covers full V
    joint_mma_kernel<<<2048, 512, DYN_SMEM>>>(dense_b, out);
}

// round 7
// speedup vs baseline: 4.6043x; 1.0012x over previous
#include <cuda_runtime.h>
#include <cuda_fp16.h>
#include <cstdint>

// Problem constants
#define BB 8
#define TT 256
#define UU 128
#define HH 512
#define II 640
#define VV 1024

// Scratch (no cudaMalloc allowed)
__device__ float  g_enc_proj[BB * TT * II];   // (2048, 640) fp32
__device__ float  g_dec_proj[BB * UU * II];   // (1024, 640) fp32
__device__ __half g_w_half[VV * II];          // W^T fp16 [v][k]

__device__ __forceinline__ uint32_t smem_u32(const void* p) {
    uint32_t a;
    asm("{ .reg .u64 t; cvta.to.shared.u64 t, %1; cvt.u32.u64 %0, t; }"
        : "=r"(a) : "l"(p));
    return a;
}

// fast tanh: 1 - 2/(exp(2x)+1) -> 2 MUFU ops, rel err ~1e-6, saturates at +-1
__device__ __forceinline__ float tanh_fast(float x) {
    float e = __expf(2.0f * x);
    return 1.0f - __fdividef(2.0f, e + 1.0f);
}

__device__ __forceinline__ void mma16816(float* c,
    uint32_t a0, uint32_t a1, uint32_t a2, uint32_t a3,
    uint32_t b0, uint32_t b1)
{
    asm volatile(
        "mma.sync.aligned.m16n8k16.row.col.f32.f16.f16.f32 "
        "{%0,%1,%2,%3}, {%4,%5,%6,%7}, {%8,%9}, {%0,%1,%2,%3};"
        : "+f"(c[0]), "+f"(c[1]), "+f"(c[2]), "+f"(c[3])
        : "r"(a0), "r"(a1), "r"(a2), "r"(a3), "r"(b0), "r"(b1));
}

__device__ __forceinline__ void ldsm4(uint32_t* r, uint32_t addr) {
    asm volatile("ldmatrix.sync.aligned.m8n8.x4.shared.b16 {%0,%1,%2,%3}, [%4];"
        : "=r"(r[0]), "=r"(r[1]), "=r"(r[2]), "=r"(r[3]) : "r"(addr));
}

__device__ __forceinline__ void cp_async16(uint32_t dst, const void* src) {
    asm volatile("cp.async.ca.shared.global [%0], [%1], 16;"
                 :: "r"(dst), "l"(src) : "memory");
}
#define CP_COMMIT() asm volatile("cp.async.commit_group;" ::: "memory")
#define CP_WAIT1()  asm volatile("cp.async.wait_group 1;" ::: "memory")

// ---------------------------------------------------------------------------
// Kernel 1: enc/dec projections. 32x64 tiles, 128 thr, grid 960 (6.5/SM).
// ---------------------------------------------------------------------------
__global__ __launch_bounds__(128) void proj_kernel(
    const float* __restrict__ enc_h, const float* __restrict__ dec_h,
    const float* __restrict__ enc_w, const float* __restrict__ enc_b,
    const float* __restrict__ dec_w, const float* __restrict__ dec_b)
{
    __shared__ float As[16][36];   // [k][row], padded
    __shared__ float Bs[16][64];   // [k][col]

    const int r0 = blockIdx.y * 32;
    const int n0 = blockIdx.x * 64;

    const float* in; const float* w; const float* bias; float* outp;
    if (r0 < BB * TT) {
        in = enc_h + (size_t)r0 * HH; w = enc_w; bias = enc_b;
        outp = g_enc_proj + (size_t)r0 * II;
    } else {
        const int r = r0 - BB * TT;
        in = dec_h + (size_t)r * HH; w = dec_w; bias = dec_b;
        outp = g_dec_proj + (size_t)r * II;
    }

    const int t  = threadIdx.x;
    const int tx = t & 15, ty = t >> 4;   // ty 0..7
    const int a_row = t >> 2;             // 0..31
    const int a_k4  = (t & 3) * 4;        // 0,4,8,12
    const int b_kk  = t >> 4;             // 0..7 (+8)
    const int b_j4  = (t & 15) * 4;       // 0..60

    float acc[4][4] = {};
    for (int k0 = 0; k0 < HH; k0 += 16) {
        float4 av = *(const float4*)(in + (size_t)a_row * HH + k0 + a_k4);
        As[a_k4 + 0][a_row] = av.x;
        As[a_k4 + 1][a_row] = av.y;
        As[a_k4 + 2][a_row] = av.z;
        As[a_k4 + 3][a_row] = av.w;
        #pragma unroll
        for (int j = 0; j < 2; j++)
            *(float4*)&Bs[b_kk + j * 8][b_j4] =
                *(const float4*)(w + (size_t)(k0 + b_kk + j * 8) * II + n0 + b_j4);
        __syncthreads();
        #pragma unroll
        for (int kk = 0; kk < 16; kk++) {
            float4 a4 = *(const float4*)&As[kk][ty * 4];
            float4 b4 = *(const float4*)&Bs[kk][tx * 4];
            float a[4] = {a4.x, a4.y, a4.z, a4.w};
            float bw[4] = {b4.x, b4.y, b4.z, b4.w};
            #pragma unroll
            for (int i = 0; i < 4; i++)
                #pragma unroll
                for (int j = 0; j < 4; j++)
                    acc[i][j] = fmaf(a[i], bw[j], acc[i][j]);
        }
        __syncthreads();
    }
    float4 bv = *(const float4*)(bias + n0 + tx * 4);
    float bb[4] = {bv.x, bv.y, bv.z, bv.w};
    #pragma unroll
    for (int i = 0; i < 4; i++) {
        float4 o;
        o.x = acc[i][0] + bb[0]; o.y = acc[i][1] + bb[1];
        o.z = acc[i][2] + bb[2]; o.w = acc[i][3] + bb[3];
        *(float4*)(outp + (size_t)(ty * 4 + i) * II + n0 + tx * 4) = o;
    }
}

// ---------------------------------------------------------------------------
// Kernel 2: dense_w (640x1024 [k][v]) -> transposed fp16 [v][k]
// ---------------------------------------------------------------------------
__global__ __launch_bounds__(256) void wsplit_kernel(const float* __restrict__ W) {
    int idx = blockIdx.x * 256 + threadIdx.x;
    int k = idx >> 10;
    int v = idx & 1023;
    g_w_half[(size_t)v * II + k] = __float2half(W[idx]);
}

// ---------------------------------------------------------------------------
// Kernel 3: fused joint GEMM. One CTA per bt, full V=1024.
// Phase 1: A panel 128x640 fp16 resident in smem (162KB).
// Mainloop: flat 80-chunk loop, 3-stage cp.async B pipeline, ldmatrix.x4,
// issue-minimal: no div/mod, incremental pointers and wrap counters.
// ---------------------------------------------------------------------------
#define A_STRIDE 1296                 // 640*2 + 16B pad (324 words, %32 = 4)
#define A_PANEL  (128 * A_STRIDE)     // 165888
#define B_STRIDE 80                   // 32*2 + 16B pad (20 words)
#define B_CHUNK  (256 * B_STRIDE)     // 20480
#define NSTAGE   3
#define DYN_SMEM (A_PANEL + NSTAGE * B_CHUNK)  // 227328
#define NCHUNK   80                   // 4 n-tiles * 20 k-chunks

__global__ __launch_bounds__(512, 1) void joint_mma_kernel(
    const float* __restrict__ dense_b, float* __restrict__ out)
{
    extern __shared__ __align__(16) char smem[];
    char* Apanel = smem;
    const uint32_t smb   = smem_u32(smem);
    const uint32_t smb_B = smb + A_PANEL;

    const int tid  = threadIdx.x;
    const int lane = tid & 31;
    const int wid  = tid >> 5;
    const int warp_m = wid & 3;    // 0..3 (M quarters of 32)
    const int warp_n = wid >> 2;   // 0..3 (N quarters of 64 within 256-tile)

    const int bt = blockIdx.x;
    const int b  = bt >> 8;

    const float* __restrict__ encp = g_enc_proj + (size_t)bt * II;
    const float* __restrict__ decp = g_dec_proj + (size_t)(b * UU) * II;

    // ---- Phase 1: build full A panel in smem (tanh + fp16 pack) ----
    {
        const int row = tid >> 2;          // 0..127
        const int kq  = tid & 3;           // 4 threads per row
        const float* dp = decp + (size_t)row * II;
        #pragma unroll 1
        for (int seg = 0; seg < 10; seg++) {
            const int k = seg * 64 + kq * 16;
            float s[16];
            #pragma unroll
            for (int q = 0; q < 4; q++) {
                float4 d = *(const float4*)(dp + k + q * 4);
                float4 e = *(const float4*)(encp + k + q * 4);
                s[q * 4 + 0] = tanh_fast(d.x + e.x);
                s[q * 4 + 1] = tanh_fast(d.y + e.y);
                s[q * 4 + 2] = tanh_fast(d.z + e.z);
                s[q * 4 + 3] = tanh_fast(d.w + e.w);
            }
            uint32_t h[8];
            #pragma unroll
            for (int q = 0; q < 8; q++) {
                __half2 hh = __floats2half2_rn(s[2 * q], s[2 * q + 1]);
                h[q] = *reinterpret_cast<uint32_t*>(&hh);
            }
            uint4* dst = (uint4*)(Apanel + row * A_STRIDE + k * 2);
            dst[0] = make_uint4(h[0], h[1], h[2], h[3]);
            dst[1] = make_uint4(h[4], h[5], h[6], h[7]);
        }
    }

    // ---- per-thread cp.async constants (two 16B transfers per chunk) ----
    // idx j=0: nl0 = tid>>2, q0 = tid&3;  j=1: nl1 = nl0+128, q1 = q0.
    const int nl0 = tid >> 2;
    const int q0  = tid & 3;
    const __half* wt0 = g_w_half + (size_t)nl0 * II + q0 * 8;   // + 128*II for j=1
    const uint32_t d0 = (uint32_t)nl0 * B_STRIDE + q0 * 16;     // + 128*B_STRIDE

    // ---- per-lane ldmatrix base offsets (validated R6) ----
    const uint32_t A_lane = smb + (uint32_t)(warp_m * 32 + (lane & 15)) * A_STRIDE
                                + (uint32_t)(lane >> 4) * 16;
    const uint32_t B_lane = (uint32_t)(warp_n * 64 + ((lane >> 4) << 3) + (lane & 7)) * B_STRIDE
                          + (uint32_t)((lane >> 3) & 1) * 16;

    float acc[2][8][4];
    #pragma unroll
    for (int i = 0; i < 2; i++)
        #pragma unroll
        for (int j = 0; j < 8; j++)
            #pragma unroll
            for (int l = 0; l < 4; l++) acc[i][j][l] = 0.0f;

    __syncthreads();   // A panel ready

    // Prologue: chunks 0 (k0=0) and 1 (k0=32) into stages 0,1
    cp_async16(smb_B + d0,                       wt0);
    cp_async16(smb_B + d0 + 128 * B_STRIDE,      wt0 + 128 * II);
    CP_COMMIT();
    cp_async16(smb_B + B_CHUNK + d0,                  wt0 + 32);
    cp_async16(smb_B + B_CHUNK + d0 + 128 * B_STRIDE, wt0 + 128 * II + 32);
    CP_COMMIT();
    CP_WAIT1();        // chunk 0 landed
    __syncthreads();

    // wrap-around loop state (no div/mod in the loop)
    const __half* wp = wt0 + 64;   // prefetch source for chunk 2
    int pk     = 2;                // prefetch k-chunk index within n-tile
    int pstage = 2;                // prefetch stage
    int stage  = 0;                // stage of current chunk
    int kc     = 0;                // k-chunk of current chunk
    int n0cur  = 0;                // n-tile base of current chunk
    int remain = NCHUNK - 2;       // prefetches left

    #pragma unroll 1
    for (int c = 0; c < NCHUNK; c++) {
        // prefetch chunk c+2
        if (remain > 0) {
            remain--;
            const uint32_t dstb = smb_B + (uint32_t)pstage * B_CHUNK + d0;
            cp_async16(dstb,                  wp);
            cp_async16(dstb + 128 * B_STRIDE, wp + 128 * II);
            wp += 32;
            if (++pk == 20) { pk = 0; wp += 256 * II - 640; }
            if (++pstage == NSTAGE) pstage = 0;
        }
        CP_COMMIT();

        // ---- MMA on chunk c ----
        const uint32_t Bbase = smb_B + (uint32_t)stage * B_CHUNK + B_lane;
        const uint32_t Abase = A_lane + (uint32_t)kc * 64;
        #pragma unroll
        for (int ks = 0; ks < 2; ks++) {
            uint32_t a0[4], a1[4];
            ldsm4(a0, Abase + ks * 32);                      // mt 0
            ldsm4(a1, Abase + ks * 32 + 16 * A_STRIDE);      // mt 1
            uint32_t bf[4][4];
            #pragma unroll
            for (int ntp = 0; ntp < 4; ntp++)
                ldsm4(bf[ntp], Bbase + ntp * (16 * B_STRIDE) + ks * 32);
            #pragma unroll
            for (int ntp = 0; ntp < 4; ntp++) {
                mma16816(acc[0][2 * ntp + 0], a0[0], a0[1], a0[2], a0[3], bf[ntp][0], bf[ntp][1]);
                mma16816(acc[0][2 * ntp + 1], a0[0], a0[1], a0[2], a0[3], bf[ntp][2], bf[ntp][3]);
                mma16816(acc[1][2 * ntp + 0], a1[0], a1[1], a1[2], a1[3], bf[ntp][0], bf[ntp][1]);
                mma16816(acc[1][2 * ntp + 1], a1[0], a1[1], a1[2], a1[3], bf[ntp][2], bf[ntp][3]);
            }
        }

        // ---- epilogue at n-tile boundary ----
        if (kc == 19) {
            #pragma unroll
            for (int mt = 0; mt < 2; mt++) {
                const int r = warp_m * 32 + mt * 16 + (lane >> 2);
                float* o0 = out + ((size_t)bt * 128 + r) * VV;
                #pragma unroll
                for (int nt = 0; nt < 8; nt++) {
                    const int col = n0cur + warp_n * 64 + nt * 8 + (lane & 3) * 2;
                    float2 bb = *(const float2*)(dense_b + col);
                    float2 v0 = make_float2(acc[mt][nt][0] + bb.x, acc[mt][nt][1] + bb.y);
                    float2 v1 = make_float2(acc[mt][nt][2] + bb.x, acc[mt][nt][3] + bb.y);
                    *(float2*)(o0 + col) = v0;
                    *(float2*)(o0 + (size_t)8 * VV + col) = v1;
                    #pragma unroll
                    for (int l = 0; l < 4; l++) acc[mt][nt][l] = 0.0f;
                }
            }
            n0cur += 256;
            kc = -1;   // -> 0 after increment
        }
        kc++;
        if (++stage == NSTAGE) stage = 0;

        CP_WAIT1();      // chunk c+1 landed
        __syncthreads(); // publish + protect stage reuse
    }
}

// ---------------------------------------------------------------------------
extern "C" void kernel_launch(void* const* d_in, const int* in_sizes, int n_in,
                              void* d_out, int out_size) {
    const float* enc_h   = (const float*)d_in[0];
    const float* dec_h   = (const float*)d_in[1];
    const float* enc_w   = (const float*)d_in[2];
    const float* enc_b   = (const float*)d_in[3];
    const float* dec_w   = (const float*)d_in[4];
    const float* dec_b   = (const float*)d_in[5];
    const float* dense_w = (const float*)d_in[6];
    const float* dense_b = (const float*)d_in[7];
    float* out = (float*)d_out;

    static bool attr_set = false;
    if (!attr_set) {
        cudaFuncSetAttribute(joint_mma_kernel,
                             cudaFuncAttributeMaxDynamicSharedMemorySize, DYN_SMEM);
        attr_set = true;
    }

    proj_kernel<<<dim3(10, 96), 128>>>(enc_h, dec_h, enc_w, enc_b, dec_w, dec_b);
    wsplit_kernel<<<(II * VV) / 256, 256>>>(dense_w);
    // one CTA per bt; each covers full V
    joint_mma_kernel<<<2048, 512, DYN_SMEM>>>(dense_b, out);
}

// round 8
// speedup vs baseline: 4.8649x; 1.0566x over previous
#include <cuda_runtime.h>
#include <cuda_fp16.h>
#include <cstdint>

// Problem constants
#define BB 8
#define TT 256
#define UU 128
#define HH 512
#define II 640
#define VV 1024

// Scratch (no cudaMalloc allowed)
__device__ float  g_enc_proj[BB * TT * II];   // (2048, 640) fp32
__device__ float  g_dec_proj[BB * UU * II];   // (1024, 640) fp32
__device__ __half g_w_half[VV * II];          // W^T fp16 [v][k]

__device__ __forceinline__ uint32_t smem_u32(const void* p) {
    uint32_t a;
    asm("{ .reg .u64 t; cvta.to.shared.u64 t, %1; cvt.u32.u64 %0, t; }"
        : "=r"(a) : "l"(p));
    return a;
}

// fast tanh: 1 - 2/(exp(2x)+1) -> 2 MUFU ops, rel err ~1e-6, saturates at +-1
__device__ __forceinline__ float tanh_fast(float x) {
    float e = __expf(2.0f * x);
    return 1.0f - __fdividef(2.0f, e + 1.0f);
}

__device__ __forceinline__ void mma16816(float* c,
    uint32_t a0, uint32_t a1, uint32_t a2, uint32_t a3,
    uint32_t b0, uint32_t b1)
{
    asm volatile(
        "mma.sync.aligned.m16n8k16.row.col.f32.f16.f16.f32 "
        "{%0,%1,%2,%3}, {%4,%5,%6,%7}, {%8,%9}, {%0,%1,%2,%3};"
        : "+f"(c[0]), "+f"(c[1]), "+f"(c[2]), "+f"(c[3])
        : "r"(a0), "r"(a1), "r"(a2), "r"(a3), "r"(b0), "r"(b1));
}

__device__ __forceinline__ void ldsm4(uint32_t* r, uint32_t addr) {
    asm volatile("ldmatrix.sync.aligned.m8n8.x4.shared.b16 {%0,%1,%2,%3}, [%4];"
        : "=r"(r[0]), "=r"(r[1]), "=r"(r[2]), "=r"(r[3]) : "r"(addr));
}

__device__ __forceinline__ void cp_async16(uint32_t dst, const void* src) {
    asm volatile("cp.async.ca.shared.global [%0], [%1], 16;"
                 :: "r"(dst), "l"(src) : "memory");
}
#define CP_COMMIT() asm volatile("cp.async.commit_group;" ::: "memory")
#define CP_WAIT1()  asm volatile("cp.async.wait_group 1;" ::: "memory")

// ---------------------------------------------------------------------------
// Kernel 1: enc/dec projections. 32x64 tiles, 128 thr, grid 960.
// ---------------------------------------------------------------------------
__global__ __launch_bounds__(128) void proj_kernel(
    const float* __restrict__ enc_h, const float* __restrict__ dec_h,
    const float* __restrict__ enc_w, const float* __restrict__ enc_b,
    const float* __restrict__ dec_w, const float* __restrict__ dec_b)
{
    __shared__ float As[16][36];
    __shared__ float Bs[16][64];

    const int r0 = blockIdx.y * 32;
    const int n0 = blockIdx.x * 64;

    const float* in; const float* w; const float* bias; float* outp;
    if (r0 < BB * TT) {
        in = enc_h + (size_t)r0 * HH; w = enc_w; bias = enc_b;
        outp = g_enc_proj + (size_t)r0 * II;
    } else {
        const int r = r0 - BB * TT;
        in = dec_h + (size_t)r * HH; w = dec_w; bias = dec_b;
        outp = g_dec_proj + (size_t)r * II;
    }

    const int t  = threadIdx.x;
    const int tx = t & 15, ty = t >> 4;
    const int a_row = t >> 2;
    const int a_k4  = (t & 3) * 4;
    const int b_kk  = t >> 4;
    const int b_j4  = (t & 15) * 4;

    float acc[4][4] = {};
    for (int k0 = 0; k0 < HH; k0 += 16) {
        float4 av = *(const float4*)(in + (size_t)a_row * HH + k0 + a_k4);
        As[a_k4 + 0][a_row] = av.x;
        As[a_k4 + 1][a_row] = av.y;
        As[a_k4 + 2][a_row] = av.z;
        As[a_k4 + 3][a_row] = av.w;
        #pragma unroll
        for (int j = 0; j < 2; j++)
            *(float4*)&Bs[b_kk + j * 8][b_j4] =
                *(const float4*)(w + (size_t)(k0 + b_kk + j * 8) * II + n0 + b_j4);
        __syncthreads();
        #pragma unroll
        for (int kk = 0; kk < 16; kk++) {
            float4 a4 = *(const float4*)&As[kk][ty * 4];
            float4 b4 = *(const float4*)&Bs[kk][tx * 4];
            float a[4] = {a4.x, a4.y, a4.z, a4.w};
            float bw[4] = {b4.x, b4.y, b4.z, b4.w};
            #pragma unroll
            for (int i = 0; i < 4; i++)
                #pragma unroll
                for (int j = 0; j < 4; j++)
                    acc[i][j] = fmaf(a[i], bw[j], acc[i][j]);
        }
        __syncthreads();
    }
    float4 bv = *(const float4*)(bias + n0 + tx * 4);
    float bb[4] = {bv.x, bv.y, bv.z, bv.w};
    #pragma unroll
    for (int i = 0; i < 4; i++) {
        float4 o;
        o.x = acc[i][0] + bb[0]; o.y = acc[i][1] + bb[1];
        o.z = acc[i][2] + bb[2]; o.w = acc[i][3] + bb[3];
        *(float4*)(outp + (size_t)(ty * 4 + i) * II + n0 + tx * 4) = o;
    }
}

// ---------------------------------------------------------------------------
// Kernel 2: dense_w (640x1024 [k][v]) -> transposed fp16 [v][k]
// ---------------------------------------------------------------------------
__global__ __launch_bounds__(256) void wsplit_kernel(const float* __restrict__ W) {
    int idx = blockIdx.x * 256 + threadIdx.x;
    int k = idx >> 10;
    int v = idx & 1023;
    g_w_half[(size_t)v * II + k] = __float2half(W[idx]);
}

// ---------------------------------------------------------------------------
// Kernel 3: fused joint GEMM, 2 CTAs/SM.
// CTA = 64 u-rows x full V=1024. 256 thr / 8 warps, warp tile 32x32.
// A panel 64x640 fp16, XOR-16B swizzled (stride 1280, unit^=row&7) -> 80KB.
// B: 3-stage cp.async pipeline, 128-row n-tiles, 10KB/stage.
// Total smem 110KB/CTA -> 2 resident CTAs fill each other's pipe gaps.
// ---------------------------------------------------------------------------
#define A_STRIDE 1280                 // 640*2, no pad; XOR swizzle instead
#define A_PANEL  (64 * A_STRIDE)      // 81920
#define B_STRIDE 80                   // 32*2 + 16B pad (20 words)
#define B_CHUNK  (128 * B_STRIDE)     // 10240
#define NSTAGE   3
#define DYN_SMEM (A_PANEL + NSTAGE * B_CHUNK)  // 112640
#define NCHUNK   160                  // 8 n-tiles * 20 k-chunks

__global__ __launch_bounds__(256, 2) void joint_mma_kernel(
    const float* __restrict__ dense_b, float* __restrict__ out)
{
    extern __shared__ __align__(16) char smem[];
    const uint32_t smb   = smem_u32(smem);
    const uint32_t smb_B = smb + A_PANEL;

    const int tid  = threadIdx.x;
    const int lane = tid & 31;
    const int wid  = tid >> 5;
    const int warp_m = wid & 1;    // 0..1 (M halves of 32)
    const int warp_n = wid >> 1;   // 0..3 (N quarters of 32 within 128-tile)

    const int bt    = blockIdx.x >> 1;
    const int urow0 = (blockIdx.x & 1) * 64;
    const int b     = bt >> 8;

    const float* __restrict__ encp = g_enc_proj + (size_t)bt * II;
    const float* __restrict__ decp = g_dec_proj + (size_t)(b * UU + urow0) * II;

    // ---- per-thread cp.async constants (two 16B transfers per chunk) ----
    const int nl0 = tid >> 2;          // 0..63 (+64 for second)
    const int q0  = tid & 3;
    const __half* wt0 = g_w_half + (size_t)nl0 * II + q0 * 8;   // + 64*II for j=1
    const uint32_t d0 = (uint32_t)nl0 * B_STRIDE + q0 * 16;     // + 64*B_STRIDE

    // Prologue BEFORE phase 1: chunks 0 (k0=0) and 1 (k0=32) into stages 0,1
    cp_async16(smb_B + d0,                      wt0);
    cp_async16(smb_B + d0 + 64 * B_STRIDE,      wt0 + (size_t)64 * II);
    CP_COMMIT();
    cp_async16(smb_B + B_CHUNK + d0,                 wt0 + 32);
    cp_async16(smb_B + B_CHUNK + d0 + 64 * B_STRIDE, wt0 + (size_t)64 * II + 32);
    CP_COMMIT();

    // ---- Phase 1: A panel 64x640 tanh+fp16, XOR-swizzled stores ----
    {
        const int row = tid >> 2;          // 0..63
        const int kq  = tid & 3;
        const int rsw = row & 7;
        char* rowp = smem + row * A_STRIDE;
        const float* dp = decp + (size_t)row * II;
        #pragma unroll 1
        for (int seg = 0; seg < 10; seg++) {
            const int k = seg * 64 + kq * 16;
            float s[16];
            #pragma unroll
            for (int q = 0; q < 4; q++) {
                float4 d = *(const float4*)(dp + k + q * 4);
                float4 e = *(const float4*)(encp + k + q * 4);
                s[q * 4 + 0] = tanh_fast(d.x + e.x);
                s[q * 4 + 1] = tanh_fast(d.y + e.y);
                s[q * 4 + 2] = tanh_fast(d.z + e.z);
                s[q * 4 + 3] = tanh_fast(d.w + e.w);
            }
            uint32_t h[8];
            #pragma unroll
            for (int q = 0; q < 8; q++) {
                __half2 hh = __floats2half2_rn(s[2 * q], s[2 * q + 1]);
                h[q] = *reinterpret_cast<uint32_t*>(&hh);
            }
            const int ub = seg * 8 + kq * 2;     // 16B unit index
            *(uint4*)(rowp + (((ub + 0) ^ rsw) << 4)) = make_uint4(h[0], h[1], h[2], h[3]);
            *(uint4*)(rowp + (((ub + 1) ^ rsw) << 4)) = make_uint4(h[4], h[5], h[6], h[7]);
        }
    }

    // ---- per-lane ldmatrix bases ----
    // A: logical row = warp_m*32 + mt*16 + (lane&15); koffset (lane>>4)*16B.
    const int a_row = warp_m * 32 + (lane & 15);
    const uint32_t A_row0 = smb + (uint32_t)a_row * A_STRIDE;             // mt 0
    const uint32_t A_row1 = A_row0 + 16 * A_STRIDE;                       // mt 1
    const int a_rsw0 = a_row & 7;
    const int a_rsw1 = (a_row + 16) & 7;   // == a_rsw0 (16 = 2*8), kept explicit
    const int a_ulane = (lane >> 4);        // unit offset from k-half
    // B: row = warp_n*32 + ((lane>>4)<<3) + (lane&7); koff = ((lane>>3)&1)*16.
    const uint32_t B_lane = (uint32_t)(warp_n * 32 + ((lane >> 4) << 3) + (lane & 7)) * B_STRIDE
                          + (uint32_t)((lane >> 3) & 1) * 16;

    float acc[2][4][4];
    #pragma unroll
    for (int i = 0; i < 2; i++)
        #pragma unroll
        for (int j = 0; j < 4; j++)
            #pragma unroll
            for (int l = 0; l < 4; l++) acc[i][j][l] = 0.0f;

    CP_WAIT1();        // chunk 0 landed
    __syncthreads();   // A panel + B chunk 0 ready

    // wrap-around loop state (no div/mod)
    const __half* wp = wt0 + 64;   // prefetch source for chunk 2
    int pk     = 2;                // prefetch k-chunk within n-tile
    int pstage = 2;
    int stage  = 0;
    int kc     = 0;                // k-chunk of current chunk
    int n0cur  = 0;                // current n-tile base column
    int remain = NCHUNK - 2;

    #pragma unroll 1
    for (int c = 0; c < NCHUNK; c++) {
        // prefetch chunk c+2
        if (remain > 0) {
            remain--;
            const uint32_t dstb = smb_B + (uint32_t)pstage * B_CHUNK + d0;
            cp_async16(dstb,                 wp);
            cp_async16(dstb + 64 * B_STRIDE, wp + (size_t)64 * II);
            wp += 32;
            if (++pk == 20) { pk = 0; wp += (size_t)128 * II - 640; }
            if (++pstage == NSTAGE) pstage = 0;
        }
        CP_COMMIT();

        // ---- MMA on chunk c ----
        const uint32_t Bbase = smb_B + (uint32_t)stage * B_CHUNK + B_lane;
        const int ub = kc * 4 + a_ulane;       // A unit base for this chunk
        #pragma unroll
        for (int ks = 0; ks < 2; ks++) {
            uint32_t a0[4], a1[4];
            const int u = ub + ks * 2;
            ldsm4(a0, A_row0 + (uint32_t)((u ^ a_rsw0) << 4));   // mt 0
            ldsm4(a1, A_row1 + (uint32_t)((u ^ a_rsw1) << 4));   // mt 1
            uint32_t bf[2][4];
            #pragma unroll
            for (int ntp = 0; ntp < 2; ntp++)
                ldsm4(bf[ntp], Bbase + ntp * (16 * B_STRIDE) + ks * 32);
            #pragma unroll
            for (int ntp = 0; ntp < 2; ntp++) {
                mma16816(acc[0][2 * ntp + 0], a0[0], a0[1], a0[2], a0[3], bf[ntp][0], bf[ntp][1]);
                mma16816(acc[0][2 * ntp + 1], a0[0], a0[1], a0[2], a0[3], bf[ntp][2], bf[ntp][3]);
                mma16816(acc[1][2 * ntp + 0], a1[0], a1[1], a1[2], a1[3], bf[ntp][0], bf[ntp][1]);
                mma16816(acc[1][2 * ntp + 1], a1[0], a1[1], a1[2], a1[3], bf[ntp][2], bf[ntp][3]);
            }
        }

        // ---- epilogue at n-tile boundary ----
        if (kc == 19) {
            #pragma unroll
            for (int mt = 0; mt < 2; mt++) {
                const int r = warp_m * 32 + mt * 16 + (lane >> 2);
                float* o0 = out + ((size_t)bt * 128 + urow0 + r) * VV;
                #pragma unroll
                for (int nt = 0; nt < 4; nt++) {
                    const int col = n0cur + warp_n * 32 + nt * 8 + (lane & 3) * 2;
                    float2 bb = *(const float2*)(dense_b + col);
                    float2 v0 = make_float2(acc[mt][nt][0] + bb.x, acc[mt][nt][1] + bb.y);
                    float2 v1 = make_float2(acc[mt][nt][2] + bb.x, acc[mt][nt][3] + bb.y);
                    *(float2*)(o0 + col) = v0;
                    *(float2*)(o0 + (size_t)8 * VV + col) = v1;
                    #pragma unroll
                    for (int l = 0; l < 4; l++) acc[mt][nt][l] = 0.0f;
                }
            }
            n0cur += 128;
            kc = -1;   // -> 0 after increment
        }
        kc++;
        if (++stage == NSTAGE) stage = 0;

        CP_WAIT1();      // chunk c+1 landed
        __syncthreads(); // publish + protect stage reuse
    }
}

// ---------------------------------------------------------------------------
extern "C" void kernel_launch(void* const* d_in, const int* in_sizes, int n_in,
                              void* d_out, int out_size) {
    const float* enc_h   = (const float*)d_in[0];
    const float* dec_h   = (const float*)d_in[1];
    const float* enc_w   = (const float*)d_in[2];
    const float* enc_b   = (const float*)d_in[3];
    const float* dec_w   = (const float*)d_in[4];
    const float* dec_b   = (const float*)d_in[5];
    const float* dense_w = (const float*)d_in[6];
    const float* dense_b = (const float*)d_in[7];
    float* out = (float*)d_out;

    static bool attr_set = false;
    if (!attr_set) {
        cudaFuncSetAttribute(joint_mma_kernel,
                             cudaFuncAttributeMaxDynamicSharedMemorySize, DYN_SMEM);
        attr_set = true;
    }

    proj_kernel<<<dim3(10, 96), 128>>>(enc_h, dec_h, enc_w, enc_b, dec_w, dec_b);
    wsplit_kernel<<<(II * VV) / 256, 256>>>(dense_w);
    // 4096 CTAs: (bt, u-half); each covers full V. 2 CTAs resident per SM.
    joint_mma_kernel<<<4096, 256, DYN_SMEM>>>(dense_b, out);
}